// round 1
// baseline (speedup 1.0000x reference)
#include <cuda_runtime.h>
#include <cuda_bf16.h>

#define H 256
#define F_MAX 300032          // >= 3*N-8 for N=100000, float4-aligned
#define PBLK 512              // max GEMV column-chunk blocks
#define COLS 1024             // feature columns per GEMV block

// Scratch (no allocations allowed in kernel_launch)
__device__ __align__(16) float g_x[F_MAX];
__device__ float g_partial[PBLK * H];   // [blk][h] layout -> coalesced reduce

// ---------------------------------------------------------------------------
// Kernel 1: featurization. x = [cos(angles) | cos(dihedrals) | sin(dihedrals)]
// cos(atan2(y,x)) = x * rsqrt(x^2+y^2), sin likewise.
// ---------------------------------------------------------------------------
__global__ void feat_kernel(const float* __restrict__ pos,
                            const int* __restrict__ aidx,
                            const int* __restrict__ didx,
                            int A, int D) {
    int t = blockIdx.x * blockDim.x + threadIdx.x;
    if (t < A) {
        int i0 = aidx[3 * t + 0], i1 = aidx[3 * t + 1], i2 = aidx[3 * t + 2];
        float p0x = pos[3 * i0], p0y = pos[3 * i0 + 1], p0z = pos[3 * i0 + 2];
        float p1x = pos[3 * i1], p1y = pos[3 * i1 + 1], p1z = pos[3 * i1 + 2];
        float p2x = pos[3 * i2], p2y = pos[3 * i2 + 1], p2z = pos[3 * i2 + 2];
        float v0x = p0x - p1x, v0y = p0y - p1y, v0z = p0z - p1z;
        float v1x = p2x - p1x, v1y = p2y - p1y, v1z = p2z - p1z;
        float d = v0x * v1x + v0y * v1y + v0z * v1z;
        float cx = v0y * v1z - v0z * v1y;
        float cy = v0z * v1x - v0x * v1z;
        float cz = v0x * v1y - v0y * v1x;
        float cr2 = cx * cx + cy * cy + cz * cz;
        g_x[t] = d * rsqrtf(fmaf(d, d, cr2));
    } else if (t < A + D) {
        int j = t - A;
        int i0 = didx[4 * j + 0], i1 = didx[4 * j + 1];
        int i2 = didx[4 * j + 2], i3 = didx[4 * j + 3];
        float p0x = pos[3 * i0], p0y = pos[3 * i0 + 1], p0z = pos[3 * i0 + 2];
        float p1x = pos[3 * i1], p1y = pos[3 * i1 + 1], p1z = pos[3 * i1 + 2];
        float p2x = pos[3 * i2], p2y = pos[3 * i2 + 1], p2z = pos[3 * i2 + 2];
        float p3x = pos[3 * i3], p3y = pos[3 * i3 + 1], p3z = pos[3 * i3 + 2];
        float b1x = p1x - p0x, b1y = p1y - p0y, b1z = p1z - p0z;
        float b2x = p2x - p1x, b2y = p2y - p1y, b2z = p2z - p1z;
        float b3x = p3x - p2x, b3y = p3y - p2y, b3z = p3z - p2z;
        // n1 = b1 x b2 ; n2 = b2 x b3
        float n1x = b1y * b2z - b1z * b2y;
        float n1y = b1z * b2x - b1x * b2z;
        float n1z = b1x * b2y - b1y * b2x;
        float n2x = b2y * b3z - b2z * b3y;
        float n2y = b2z * b3x - b2x * b3z;
        float n2z = b2x * b3y - b2y * b3x;
        float xd = n1x * n2x + n1y * n2y + n1z * n2z;       // dot(n1,n2)
        // m = n1 x n2
        float mx = n1y * n2z - n1z * n2y;
        float my = n1z * n2x - n1x * n2z;
        float mz = n1x * n2y - n1y * n2x;
        float b2n2 = b2x * b2x + b2y * b2y + b2z * b2z;
        float yd = (mx * b2x + my * b2y + mz * b2z) * rsqrtf(b2n2);
        float r = rsqrtf(fmaf(xd, xd, yd * yd));
        g_x[A + j]     = xd * r;   // cos(dihedral)
        g_x[A + D + j] = yd * r;   // sin(dihedral)
    }
}

// ---------------------------------------------------------------------------
// Kernel 2: y1_partial = W1[:, chunk] @ x[chunk].  Streams 307 MB of W1 once.
// Each block: 1024 columns staged in smem, 8 warps x 32 rows, float4 loads.
// ---------------------------------------------------------------------------
__global__ void __launch_bounds__(256) gemv_kernel(const float* __restrict__ W1,
                                                   int F) {
    __shared__ float4 xs[COLS / 4];   // 4 KB
    int blk = blockIdx.x;
    int f0 = blk * COLS;
    int ncols = F - f0;
    if (ncols > COLS) ncols = COLS;
    int nc4 = ncols >> 2;
    int rem = ncols & 3;

    const float4* xg = (const float4*)(g_x + f0);
    for (int i = threadIdx.x; i < COLS / 4; i += blockDim.x)
        xs[i] = (i < nc4) ? xg[i] : make_float4(0.f, 0.f, 0.f, 0.f);
    __syncthreads();

    int warp = threadIdx.x >> 5, lane = threadIdx.x & 31;
    for (int h = warp; h < H; h += 8) {
        const float* Wrow = W1 + (size_t)h * F + f0;
        const float4* Wr4 = (const float4*)Wrow;
        float a0 = 0.f, a1 = 0.f;
#pragma unroll
        for (int k = 0; k < 8; k += 2) {
            int i0 = k * 32 + lane;
            int i1 = (k + 1) * 32 + lane;
            if (i0 < nc4) {
                float4 w = Wr4[i0], x = xs[i0];
                a0 += w.x * x.x + w.y * x.y + w.z * x.z + w.w * x.w;
            }
            if (i1 < nc4) {
                float4 w = Wr4[i1], x = xs[i1];
                a1 += w.x * x.x + w.y * x.y + w.z * x.z + w.w * x.w;
            }
        }
        float acc = a0 + a1;
        if (rem && lane == 0) {   // scalar tail (only possible in last block)
            for (int r = 0; r < rem; r++)
                acc += Wrow[nc4 * 4 + r] * g_x[f0 + nc4 * 4 + r];
        }
#pragma unroll
        for (int o = 16; o; o >>= 1) acc += __shfl_xor_sync(0xffffffffu, acc, o);
        if (lane == 0) g_partial[blk * H + h] = acc;
    }
}

// ---------------------------------------------------------------------------
// Kernel 3: deterministic reduce + b1 + tanh, then the two 256x256 layers and
// the final W4 dot. One block of 256 threads; all data L2-resident.
// ---------------------------------------------------------------------------
__global__ void __launch_bounds__(256) mlp_kernel(const float* __restrict__ b1,
                                                  const float* __restrict__ W2,
                                                  const float* __restrict__ b2,
                                                  const float* __restrict__ W3,
                                                  const float* __restrict__ b3,
                                                  const float* __restrict__ W4,
                                                  float* __restrict__ out,
                                                  int nblk) {
    __shared__ float sa[H], sb[H];
    int tid = threadIdx.x;
    int warp = tid >> 5, lane = tid & 31;

    // fixed-order reduction of GEMV partials (coalesced: [blk][h])
    float acc = 0.f;
    for (int k = 0; k < nblk; k++) acc += g_partial[k * H + tid];
    sa[tid] = tanhf(acc + b1[tid]);
    __syncthreads();

    // layer 2: sb = tanh(W2 @ sa + b2)
    for (int h = warp; h < H; h += 8) {
        const float* Wr = W2 + h * H;
        float a = 0.f;
#pragma unroll
        for (int k = 0; k < 8; k++) a += Wr[lane + 32 * k] * sa[lane + 32 * k];
#pragma unroll
        for (int o = 16; o; o >>= 1) a += __shfl_xor_sync(0xffffffffu, a, o);
        if (lane == 0) sb[h] = tanhf(a + b2[h]);
    }
    __syncthreads();

    // layer 3: sa = tanh(W3 @ sb + b3)
    for (int h = warp; h < H; h += 8) {
        const float* Wr = W3 + h * H;
        float a = 0.f;
#pragma unroll
        for (int k = 0; k < 8; k++) a += Wr[lane + 32 * k] * sb[lane + 32 * k];
#pragma unroll
        for (int o = 16; o; o >>= 1) a += __shfl_xor_sync(0xffffffffu, a, o);
        if (lane == 0) sa[h] = tanhf(a + b3[h]);
    }
    __syncthreads();

    // output: KB*T * (W4 @ sa)
    if (warp == 0) {
        float a = 0.f;
#pragma unroll
        for (int k = 0; k < 8; k++) a += W4[lane + 32 * k] * sa[lane + 32 * k];
#pragma unroll
        for (int o = 16; o; o >>= 1) a += __shfl_xor_sync(0xffffffffu, a, o);
        if (lane == 0) out[0] = 0.00831446261815324f * 300.0f * a;
    }
}

// ---------------------------------------------------------------------------
extern "C" void kernel_launch(void* const* d_in, const int* in_sizes, int n_in,
                              void* d_out, int out_size) {
    const float* pos  = (const float*)d_in[0];
    const int*   aidx = (const int*)  d_in[1];
    const int*   didx = (const int*)  d_in[2];
    const float* W1   = (const float*)d_in[3];
    const float* b1   = (const float*)d_in[4];
    const float* W2   = (const float*)d_in[5];
    const float* b2   = (const float*)d_in[6];
    const float* W3   = (const float*)d_in[7];
    const float* b3   = (const float*)d_in[8];
    const float* W4   = (const float*)d_in[9];

    int A = in_sizes[1] / 3;
    int D = in_sizes[2] / 4;
    int F = A + 2 * D;
    int nt = A + D;

    feat_kernel<<<(nt + 255) / 256, 256>>>(pos, aidx, didx, A, D);

    int nblk = (F + COLS - 1) / COLS;   // 293 for N=100000
    gemv_kernel<<<nblk, 256>>>(W1, F);

    mlp_kernel<<<1, 256>>>(b1, W2, b2, W3, b3, W4, (float*)d_out, nblk);
}

// round 3
// speedup vs baseline: 1.4306x; 1.4306x over previous
#include <cuda_runtime.h>
#include <cuda_bf16.h>

#define H 256
#define F_MAX 300032          // >= 3*N-8 for N=100000, float4-aligned
#define CHUNK 8192            // feature columns per GEMV block (32 KB smem)
#define MAXCH 64              // max column chunks

// Scratch (no allocations allowed in kernel_launch)
__device__ __align__(16) float g_x[F_MAX];
__device__ float g_partial[MAXCH * H];   // [chunk][row] -> coalesced reduce

// ---------------------------------------------------------------------------
// Kernel 1: featurization. x = [cos(angles) | cos(dihedrals) | sin(dihedrals)]
// cos(atan2(y,x)) = x * rsqrt(x^2+y^2), sin likewise. Thread t computes both
// angle t and dihedral t (position loads overlap -> L1 hits).
// ---------------------------------------------------------------------------
__global__ void feat_kernel(const float* __restrict__ pos,
                            const int* __restrict__ aidx,
                            const int* __restrict__ didx,
                            int A, int D) {
    int t = blockIdx.x * blockDim.x + threadIdx.x;
    if (t < A) {
        int i0 = aidx[3 * t + 0], i1 = aidx[3 * t + 1], i2 = aidx[3 * t + 2];
        float p0x = pos[3 * i0], p0y = pos[3 * i0 + 1], p0z = pos[3 * i0 + 2];
        float p1x = pos[3 * i1], p1y = pos[3 * i1 + 1], p1z = pos[3 * i1 + 2];
        float p2x = pos[3 * i2], p2y = pos[3 * i2 + 1], p2z = pos[3 * i2 + 2];
        float v0x = p0x - p1x, v0y = p0y - p1y, v0z = p0z - p1z;
        float v1x = p2x - p1x, v1y = p2y - p1y, v1z = p2z - p1z;
        float d = v0x * v1x + v0y * v1y + v0z * v1z;
        float cx = v0y * v1z - v0z * v1y;
        float cy = v0z * v1x - v0x * v1z;
        float cz = v0x * v1y - v0y * v1x;
        float cr2 = cx * cx + cy * cy + cz * cz;
        g_x[t] = d * rsqrtf(fmaf(d, d, cr2));
    }
    if (t < D) {
        int i0 = didx[4 * t + 0], i1 = didx[4 * t + 1];
        int i2 = didx[4 * t + 2], i3 = didx[4 * t + 3];
        float p0x = pos[3 * i0], p0y = pos[3 * i0 + 1], p0z = pos[3 * i0 + 2];
        float p1x = pos[3 * i1], p1y = pos[3 * i1 + 1], p1z = pos[3 * i1 + 2];
        float p2x = pos[3 * i2], p2y = pos[3 * i2 + 1], p2z = pos[3 * i2 + 2];
        float p3x = pos[3 * i3], p3y = pos[3 * i3 + 1], p3z = pos[3 * i3 + 2];
        float b1x = p1x - p0x, b1y = p1y - p0y, b1z = p1z - p0z;
        float b2x = p2x - p1x, b2y = p2y - p1y, b2z = p2z - p1z;
        float b3x = p3x - p2x, b3y = p3y - p2y, b3z = p3z - p2z;
        float n1x = b1y * b2z - b1z * b2y;
        float n1y = b1z * b2x - b1x * b2z;
        float n1z = b1x * b2y - b1y * b2x;
        float n2x = b2y * b3z - b2z * b3y;
        float n2y = b2z * b3x - b2x * b3z;
        float n2z = b2x * b3y - b2y * b3x;
        float xd = n1x * n2x + n1y * n2y + n1z * n2z;
        float mx = n1y * n2z - n1z * n2y;
        float my = n1z * n2x - n1x * n2z;
        float mz = n1x * n2y - n1y * n2x;
        float b2n2 = b2x * b2x + b2y * b2y + b2z * b2z;
        float yd = (mx * b2x + my * b2y + mz * b2z) * rsqrtf(b2n2);
        float r = rsqrtf(fmaf(xd, xd, yd * yd));
        g_x[A + t]     = xd * r;   // cos(dihedral)
        g_x[A + D + t] = yd * r;   // sin(dihedral)
    }
}

// ---------------------------------------------------------------------------
// Kernel 2: GEMV partials. One warp = one (row, 8192-col chunk). Long
// predicate-free streaming loop, 8 independent LDG.128 in flight per warp,
// single shuffle reduce at the end. Streams 307 MB of W1 once.
// grid = (H/8, nchunks), block = 256 (8 warps, one row each).
// ---------------------------------------------------------------------------
__global__ void __launch_bounds__(256) gemv_kernel(const float* __restrict__ W1,
                                                   int F) {
    __shared__ float4 xs[CHUNK / 4];   // 32 KB
    int cidx = blockIdx.y;
    int f0 = cidx * CHUNK;
    int ncols = F - f0;
    if (ncols > CHUNK) ncols = CHUNK;
    int nc4 = ncols >> 2;              // F % 4 == 0 for this problem family

    // stage x chunk to smem (coalesced float4)
    const float4* xg = (const float4*)(g_x + f0);
    for (int i = threadIdx.x; i < nc4; i += blockDim.x) xs[i] = xg[i];
    __syncthreads();

    int warp = threadIdx.x >> 5, lane = threadIdx.x & 31;
    int row = blockIdx.x * 8 + warp;
    const float4* Wr = (const float4*)(W1 + (size_t)row * F + f0);

    float a0 = 0.f, a1 = 0.f, a2 = 0.f, a3 = 0.f;
    int n8 = nc4 - (nc4 & 255);        // multiple of 32 lanes * 8 unroll
    for (int base = 0; base < n8; base += 256) {
        int i = base + lane;
        float4 w0 = Wr[i];       float4 w1 = Wr[i + 32];
        float4 w2 = Wr[i + 64];  float4 w3 = Wr[i + 96];
        float4 w4 = Wr[i + 128]; float4 w5 = Wr[i + 160];
        float4 w6 = Wr[i + 192]; float4 w7 = Wr[i + 224];
        float4 x0 = xs[i];       float4 x1 = xs[i + 32];
        float4 x2 = xs[i + 64];  float4 x3 = xs[i + 96];
        float4 x4 = xs[i + 128]; float4 x5 = xs[i + 160];
        float4 x6 = xs[i + 192]; float4 x7 = xs[i + 224];
        a0 += w0.x*x0.x + w0.y*x0.y + w0.z*x0.z + w0.w*x0.w;
        a1 += w1.x*x1.x + w1.y*x1.y + w1.z*x1.z + w1.w*x1.w;
        a2 += w2.x*x2.x + w2.y*x2.y + w2.z*x2.z + w2.w*x2.w;
        a3 += w3.x*x3.x + w3.y*x3.y + w3.z*x3.z + w3.w*x3.w;
        a0 += w4.x*x4.x + w4.y*x4.y + w4.z*x4.z + w4.w*x4.w;
        a1 += w5.x*x5.x + w5.y*x5.y + w5.z*x5.z + w5.w*x5.w;
        a2 += w6.x*x6.x + w6.y*x6.y + w6.z*x6.z + w6.w*x6.w;
        a3 += w7.x*x7.x + w7.y*x7.y + w7.z*x7.z + w7.w*x7.w;
    }
    for (int i = n8 + lane; i < nc4; i += 32) {
        float4 w = Wr[i], x = xs[i];
        a0 += w.x*x.x + w.y*x.y + w.z*x.z + w.w*x.w;
    }

    float acc = (a0 + a2) + (a1 + a3);
#pragma unroll
    for (int o = 16; o; o >>= 1) acc += __shfl_xor_sync(0xffffffffu, acc, o);
    if (lane == 0) g_partial[cidx * H + row] = acc;
}

// ---------------------------------------------------------------------------
// Kernel 3: deterministic reduce + b1 + tanh, then the two 256x256 layers and
// the final W4 dot. One block of 256 threads; all data L2-resident.
// ---------------------------------------------------------------------------
__global__ void __launch_bounds__(256) mlp_kernel(const float* __restrict__ b1,
                                                  const float* __restrict__ W2,
                                                  const float* __restrict__ b2,
                                                  const float* __restrict__ W3,
                                                  const float* __restrict__ b3,
                                                  const float* __restrict__ W4,
                                                  float* __restrict__ out,
                                                  int nch) {
    __shared__ float sa[H], sb[H];
    int tid = threadIdx.x;
    int warp = tid >> 5, lane = tid & 31;

    // fixed-order reduction of GEMV partials (coalesced: [chunk][row])
    float acc = 0.f;
    for (int k = 0; k < nch; k++) acc += g_partial[k * H + tid];
    sa[tid] = tanhf(acc + b1[tid]);
    __syncthreads();

    for (int h = warp; h < H; h += 8) {
        const float* Wr = W2 + h * H;
        float a = 0.f;
#pragma unroll
        for (int k = 0; k < 8; k++) a += Wr[lane + 32 * k] * sa[lane + 32 * k];
#pragma unroll
        for (int o = 16; o; o >>= 1) a += __shfl_xor_sync(0xffffffffu, a, o);
        if (lane == 0) sb[h] = tanhf(a + b2[h]);
    }
    __syncthreads();

    for (int h = warp; h < H; h += 8) {
        const float* Wr = W3 + h * H;
        float a = 0.f;
#pragma unroll
        for (int k = 0; k < 8; k++) a += Wr[lane + 32 * k] * sb[lane + 32 * k];
#pragma unroll
        for (int o = 16; o; o >>= 1) a += __shfl_xor_sync(0xffffffffu, a, o);
        if (lane == 0) sa[h] = tanhf(a + b3[h]);
    }
    __syncthreads();

    if (warp == 0) {
        float a = 0.f;
#pragma unroll
        for (int k = 0; k < 8; k++) a += W4[lane + 32 * k] * sa[lane + 32 * k];
#pragma unroll
        for (int o = 16; o; o >>= 1) a += __shfl_xor_sync(0xffffffffu, a, o);
        if (lane == 0) out[0] = 0.00831446261815324f * 300.0f * a;
    }
}

// ---------------------------------------------------------------------------
extern "C" void kernel_launch(void* const* d_in, const int* in_sizes, int n_in,
                              void* d_out, int out_size) {
    const float* pos  = (const float*)d_in[0];
    const int*   aidx = (const int*)  d_in[1];
    const int*   didx = (const int*)  d_in[2];
    const float* W1   = (const float*)d_in[3];
    const float* b1   = (const float*)d_in[4];
    const float* W2   = (const float*)d_in[5];
    const float* b2   = (const float*)d_in[6];
    const float* W3   = (const float*)d_in[7];
    const float* b3   = (const float*)d_in[8];
    const float* W4   = (const float*)d_in[9];

    int A = in_sizes[1] / 3;
    int D = in_sizes[2] / 4;
    int F = A + 2 * D;

    feat_kernel<<<(A + 255) / 256, 256>>>(pos, aidx, didx, A, D);

    int nch = (F + CHUNK - 1) / CHUNK;   // 37 for N=100000
    dim3 grid(H / 8, nch);
    gemv_kernel<<<grid, 256>>>(W1, F);

    mlp_kernel<<<1, 256>>>(b1, W2, b2, W3, b3, W4, (float*)d_out, nch);
}